// round 4
// baseline (speedup 1.0000x reference)
#include <cuda_runtime.h>
#include <cstdint>

#define N_NODES 100000
#define FEAT    64
#define NF      (N_NODES * FEAT)
#define E_MAX   1700000

// Scratch: device globals (no allocations allowed).
__device__ __align__(16) float g_u[NF];
__device__ __align__(16) float g_u2[NF];
__device__ int   g_cnt[N_NODES];
__device__ int   g_off[N_NODES + 1];
__device__ int   g_cur[N_NODES];
__device__ int   g_adj[E_MAX];
__device__ float g_dinv[N_NODES];    // (deg)^{-1/2}, deg includes self-loop
__device__ float g_dinv2[N_NODES];   // (deg)^{-1}
__device__ int   g_is64;             // 1 if edge_index is int64, 0 if int32

// ---------------------------------------------------------------------------
// Deterministic dtype sniff: int64 node ids < 1e5 have zero high words.
__global__ void k_detect(const int* __restrict__ ei32) {
    __shared__ int any;
    if (threadIdx.x == 0) any = 0;
    __syncthreads();
    for (int i = threadIdx.x; i < 1024; i += blockDim.x)
        if (ei32[2 * i + 1] != 0) any = 1;     // benign race, same result
    __syncthreads();
    if (threadIdx.x == 0) g_is64 = (any == 0) ? 1 : 0;
}

__device__ __forceinline__ int edge_idx(const void* ei, int E, int half, int e) {
    if (g_is64) {
        long long v = ((const long long*)ei)[(size_t)half * E + e];
        return (int)v;
    }
    return ((const int*)ei)[(size_t)half * E + e];
}

// ---------------------------------------------------------------------------
__global__ void k_zero() {
    int i = blockIdx.x * blockDim.x + threadIdx.x;
    if (i < N_NODES) g_cnt[i] = 0;
}

__global__ void k_hist(const void* __restrict__ ei, int E) {
    int e = blockIdx.x * blockDim.x + threadIdx.x;
    if (e >= E) return;
    unsigned t = (unsigned)edge_idx(ei, E, 1, e);   // target i
    if (t < N_NODES) atomicAdd(&g_cnt[t], 1);
}

// One-block exclusive scan over g_cnt -> g_off/g_cur, plus dinv/dinv2.
__global__ void k_scan() {
    const int T = 1024;
    const int CH = (N_NODES + T - 1) / T;   // 98
    __shared__ int bs[T];
    int t = threadIdx.x;
    int beg = t * CH;
    int end = beg + CH;
    if (beg > N_NODES) beg = N_NODES;
    if (end > N_NODES) end = N_NODES;

    int s = 0;
    for (int i = beg; i < end; i++) s += g_cnt[i];
    bs[t] = s;
    __syncthreads();
    for (int off = 1; off < T; off <<= 1) {       // Hillis-Steele inclusive
        int v = (t >= off) ? bs[t - off] : 0;
        __syncthreads();
        bs[t] += v;
        __syncthreads();
    }
    int run = bs[t] - s;   // exclusive prefix
    for (int i = beg; i < end; i++) {
        g_off[i] = run;
        g_cur[i] = run;
        int c = g_cnt[i];
        float deg = (float)c + 1.0f;       // self-loop
        g_dinv[i]  = rsqrtf(deg);
        g_dinv2[i] = 1.0f / deg;
        run += c;
    }
    if (t == 0) g_off[N_NODES] = bs[T - 1];
}

__global__ void k_scatter(const void* __restrict__ ei, int E) {
    int e = blockIdx.x * blockDim.x + threadIdx.x;
    if (e >= E) return;
    unsigned tgt = (unsigned)edge_idx(ei, E, 1, e);
    unsigned src = (unsigned)edge_idx(ei, E, 0, e);
    if (tgt >= N_NODES || src >= N_NODES) return;
    int pos = atomicAdd(&g_cur[tgt], 1);
    if (pos < E_MAX) g_adj[pos] = (int)src;
}

// ---------------------------------------------------------------------------
// u0[i,:] = dinv[i] * (x[i,:] @ W^T)   -- x:[N,128], W:[64,128]
__global__ void k_gemm(const float* __restrict__ x, const float* __restrict__ W) {
    __shared__ float Ws[128 * 64];   // Ws[k*64 + c] = W[c*128 + k]
    __shared__ float xs[4][128];

    int tid = threadIdx.x;
    for (int i = tid; i < 128 * 64; i += 256) {
        int c = i >> 7, k = i & 127;
        Ws[k * 64 + c] = W[i];
    }
    __syncthreads();

    int c = tid & 63;
    int r = tid >> 6;

    for (int rb = blockIdx.x * 4; rb < N_NODES; rb += gridDim.x * 4) {
        for (int i = tid; i < 512; i += 256) {
            int rr = i >> 7, k = i & 127;
            int rowi = rb + rr;
            xs[rr][k] = (rowi < N_NODES) ? x[(size_t)rowi * 128 + k] : 0.0f;
        }
        __syncthreads();

        int rowi = rb + r;
        if (rowi < N_NODES) {
            float s = 0.0f;
            #pragma unroll
            for (int k = 0; k < 128; k++)
                s = fmaf(xs[r][k], Ws[k * 64 + c], s);
            g_u[(size_t)rowi * 64 + c] = g_dinv[rowi] * s;
        }
        __syncthreads();
    }
}

// ---------------------------------------------------------------------------
// Gather hop: 16 threads per node, one float4 column-group each.
// PASS 0: g_u  -> g_u2, scale dinv2
// PASS 1: g_u2 -> g_u,  scale dinv2
// PASS 2: g_u  -> out,  scale dinv, + bias
template <int PASS>
__global__ void k_hop(float* __restrict__ outp, const float* __restrict__ b) {
    const float4* uin  = reinterpret_cast<const float4*>(PASS == 1 ? g_u2 : g_u);
    float4* uout = (PASS == 0) ? reinterpret_cast<float4*>(g_u2)
                 : (PASS == 1) ? reinterpret_cast<float4*>(g_u)
                               : reinterpret_cast<float4*>(outp);

    int tid  = threadIdx.x;
    int node = blockIdx.x * 16 + (tid >> 4);
    if (node >= N_NODES) return;
    int c4 = tid & 15;

    int d   = g_off[node];
    int end = g_off[node + 1];

    float4 s = make_float4(0.f, 0.f, 0.f, 0.f);
    for (; d + 1 < end; d += 2) {
        int j0 = __ldg(&g_adj[d]);
        int j1 = __ldg(&g_adj[d + 1]);
        float4 a0 = __ldg(&uin[(size_t)j0 * 16 + c4]);
        float4 a1 = __ldg(&uin[(size_t)j1 * 16 + c4]);
        s.x += a0.x + a1.x;
        s.y += a0.y + a1.y;
        s.z += a0.z + a1.z;
        s.w += a0.w + a1.w;
    }
    if (d < end) {
        int j0 = __ldg(&g_adj[d]);
        float4 a0 = __ldg(&uin[(size_t)j0 * 16 + c4]);
        s.x += a0.x; s.y += a0.y; s.z += a0.z; s.w += a0.w;
    }

    float4 self = uin[(size_t)node * 16 + c4];
    s.x += self.x; s.y += self.y; s.z += self.z; s.w += self.w;

    float4 o;
    if (PASS == 2) {
        float sc = g_dinv[node];
        int cb = c4 << 2;
        o.x = sc * s.x + __ldg(&b[cb + 0]);
        o.y = sc * s.y + __ldg(&b[cb + 1]);
        o.z = sc * s.z + __ldg(&b[cb + 2]);
        o.w = sc * s.w + __ldg(&b[cb + 3]);
    } else {
        float sc = g_dinv2[node];
        o.x = sc * s.x; o.y = sc * s.y; o.z = sc * s.z; o.w = sc * s.w;
    }
    uout[(size_t)node * 16 + c4] = o;
}

// ---------------------------------------------------------------------------
extern "C" void kernel_launch(void* const* d_in, const int* in_sizes, int n_in,
                              void* d_out, int out_size) {
    const float* x  = (const float*)d_in[0];   // [100000,128]
    const void*  ei = d_in[1];                 // [2, E] int32 or int64
    const float* W  = (const float*)d_in[2];   // [64,128]
    const float* b  = (const float*)d_in[3];   // [64]
    float* out = (float*)d_out;

    const int E = in_sizes[1] / 2;             // 1,600,000

    const int T = 256;
    const int nb = (N_NODES + T - 1) / T;
    const int eb = (E + T - 1) / T;

    k_detect<<<1, 256>>>((const int*)ei);

    // CSR build (counting sort by target)
    k_zero<<<nb, T>>>();
    k_hist<<<eb, T>>>(ei, E);
    k_scan<<<1, 1024>>>();
    k_scatter<<<eb, T>>>(ei, E);

    // Input transform (linear layer folded in front; needs g_dinv from k_scan)
    k_gemm<<<2048, T>>>(x, W);

    // 3 gather hops (16 nodes per 256-thread block)
    const int hb = (N_NODES + 15) / 16;
    k_hop<0><<<hb, T>>>(nullptr, b);
    k_hop<1><<<hb, T>>>(nullptr, b);
    k_hop<2><<<hb, T>>>(out, b);
}

// round 5
// speedup vs baseline: 1.7632x; 1.7632x over previous
#include <cuda_runtime.h>
#include <cstdint>

#define N_NODES 100000
#define FEAT    64
#define NF      (N_NODES * FEAT)
#define E_MAX   1700000
#define SCAN_T  1024
#define SCAN_B  ((N_NODES + SCAN_T - 1) / SCAN_T)   // 98

// Scratch: device globals (no allocations allowed).
__device__ __align__(16) float g_u[NF];
__device__ __align__(16) float g_u2[NF];
__device__ int   g_cnt[N_NODES];
__device__ int   g_off[N_NODES + 1];
__device__ int   g_cur[N_NODES];
__device__ int   g_adj[E_MAX];
__device__ int   g_blk[SCAN_B];
__device__ float g_dinv[N_NODES];    // (deg)^{-1/2}, deg includes self-loop
__device__ float g_dinv2[N_NODES];   // (deg)^{-1}
__device__ int   g_is64;             // 1 if edge_index is int64, 0 if int32

// ---------------------------------------------------------------------------
// Deterministic dtype sniff: int64 node ids < 1e5 have zero high words.
__global__ void k_detect(const int* __restrict__ ei32) {
    __shared__ int any;
    if (threadIdx.x == 0) any = 0;
    __syncthreads();
    for (int i = threadIdx.x; i < 1024; i += blockDim.x)
        if (ei32[2 * i + 1] != 0) any = 1;     // benign race, same result
    __syncthreads();
    if (threadIdx.x == 0) g_is64 = (any == 0) ? 1 : 0;
}

__device__ __forceinline__ int edge_idx(const void* ei, int E, int half, int e) {
    if (g_is64) {
        long long v = ((const long long*)ei)[(size_t)half * E + e];
        return (int)v;
    }
    return ((const int*)ei)[(size_t)half * E + e];
}

// ---------------------------------------------------------------------------
__global__ void k_zero() {
    int i = blockIdx.x * blockDim.x + threadIdx.x;
    if (i < N_NODES) g_cnt[i] = 0;
}

__global__ void k_hist(const void* __restrict__ ei, int E) {
    int e = blockIdx.x * blockDim.x + threadIdx.x;
    if (e >= E) return;
    unsigned t = (unsigned)edge_idx(ei, E, 1, e);   // target i
    if (t < N_NODES) atomicAdd(&g_cnt[t], 1);
}

// --- grid-wide exclusive scan of g_cnt, 3 phases --------------------------
// Phase 1: per-block sum of 1024 counts.
__global__ void k_scan1() {
    __shared__ int bs[SCAN_T];
    int i = blockIdx.x * SCAN_T + threadIdx.x;
    int v = (i < N_NODES) ? g_cnt[i] : 0;
    bs[threadIdx.x] = v;
    __syncthreads();
    for (int off = SCAN_T / 2; off > 0; off >>= 1) {
        if (threadIdx.x < off) bs[threadIdx.x] += bs[threadIdx.x + off];
        __syncthreads();
    }
    if (threadIdx.x == 0) g_blk[blockIdx.x] = bs[0];
}

// Phase 2: one tiny block scans the 98 block sums (exclusive, in place).
__global__ void k_scan2() {
    __shared__ int bs[128];
    int t = threadIdx.x;
    int v = (t < SCAN_B) ? g_blk[t] : 0;
    bs[t] = v;
    __syncthreads();
    for (int off = 1; off < 128; off <<= 1) {       // Hillis-Steele inclusive
        int p = (t >= off) ? bs[t - off] : 0;
        __syncthreads();
        bs[t] += p;
        __syncthreads();
    }
    if (t < SCAN_B) g_blk[t] = bs[t] - v;           // exclusive
    if (t == 0) g_off[N_NODES] = bs[127];           // total (zeros padded)
}

// Phase 3: per-block exclusive scan + block offset; also dinv/dinv2.
__global__ void k_scan3() {
    __shared__ int bs[SCAN_T];
    int t = threadIdx.x;
    int i = blockIdx.x * SCAN_T + t;
    int c = (i < N_NODES) ? g_cnt[i] : 0;
    bs[t] = c;
    __syncthreads();
    for (int off = 1; off < SCAN_T; off <<= 1) {    // Hillis-Steele inclusive
        int p = (t >= off) ? bs[t - off] : 0;
        __syncthreads();
        bs[t] += p;
        __syncthreads();
    }
    if (i < N_NODES) {
        int excl = g_blk[blockIdx.x] + bs[t] - c;
        g_off[i] = excl;
        g_cur[i] = excl;
        float deg = (float)c + 1.0f;        // self-loop
        g_dinv[i]  = rsqrtf(deg);
        g_dinv2[i] = 1.0f / deg;
    }
}

__global__ void k_scatter(const void* __restrict__ ei, int E) {
    int e = blockIdx.x * blockDim.x + threadIdx.x;
    if (e >= E) return;
    unsigned tgt = (unsigned)edge_idx(ei, E, 1, e);
    unsigned src = (unsigned)edge_idx(ei, E, 0, e);
    if (tgt >= N_NODES || src >= N_NODES) return;
    int pos = atomicAdd(&g_cur[tgt], 1);
    if (pos < E_MAX) g_adj[pos] = (int)src;
}

// ---------------------------------------------------------------------------
// u0[i,:] = dinv[i] * (x[i,:] @ W^T)   -- x:[N,128], W:[64,128]
__global__ void k_gemm(const float* __restrict__ x, const float* __restrict__ W) {
    __shared__ float Ws[128 * 64];   // Ws[k*64 + c] = W[c*128 + k]
    __shared__ float xs[4][128];

    int tid = threadIdx.x;
    for (int i = tid; i < 128 * 64; i += 256) {
        int c = i >> 7, k = i & 127;
        Ws[k * 64 + c] = W[i];
    }
    __syncthreads();

    int c = tid & 63;
    int r = tid >> 6;

    for (int rb = blockIdx.x * 4; rb < N_NODES; rb += gridDim.x * 4) {
        for (int i = tid; i < 512; i += 256) {
            int rr = i >> 7, k = i & 127;
            int rowi = rb + rr;
            xs[rr][k] = (rowi < N_NODES) ? x[(size_t)rowi * 128 + k] : 0.0f;
        }
        __syncthreads();

        int rowi = rb + r;
        if (rowi < N_NODES) {
            float s = 0.0f;
            #pragma unroll
            for (int k = 0; k < 128; k++)
                s = fmaf(xs[r][k], Ws[k * 64 + c], s);
            g_u[(size_t)rowi * 64 + c] = g_dinv[rowi] * s;
        }
        __syncthreads();
    }
}

// ---------------------------------------------------------------------------
// Gather hop: 16 threads per node, one float4 column-group each.
// PASS 0: g_u  -> g_u2, scale dinv2
// PASS 1: g_u2 -> g_u,  scale dinv2
// PASS 2: g_u  -> out,  scale dinv, + bias
template <int PASS>
__global__ void k_hop(float* __restrict__ outp, const float* __restrict__ b) {
    const float4* uin  = reinterpret_cast<const float4*>(PASS == 1 ? g_u2 : g_u);
    float4* uout = (PASS == 0) ? reinterpret_cast<float4*>(g_u2)
                 : (PASS == 1) ? reinterpret_cast<float4*>(g_u)
                               : reinterpret_cast<float4*>(outp);

    int tid  = threadIdx.x;
    int node = blockIdx.x * 16 + (tid >> 4);
    if (node >= N_NODES) return;
    int c4 = tid & 15;

    int d   = g_off[node];
    int end = g_off[node + 1];

    float4 s = make_float4(0.f, 0.f, 0.f, 0.f);
    for (; d + 1 < end; d += 2) {
        int j0 = __ldg(&g_adj[d]);
        int j1 = __ldg(&g_adj[d + 1]);
        float4 a0 = __ldg(&uin[(size_t)j0 * 16 + c4]);
        float4 a1 = __ldg(&uin[(size_t)j1 * 16 + c4]);
        s.x += a0.x + a1.x;
        s.y += a0.y + a1.y;
        s.z += a0.z + a1.z;
        s.w += a0.w + a1.w;
    }
    if (d < end) {
        int j0 = __ldg(&g_adj[d]);
        float4 a0 = __ldg(&uin[(size_t)j0 * 16 + c4]);
        s.x += a0.x; s.y += a0.y; s.z += a0.z; s.w += a0.w;
    }

    float4 self = uin[(size_t)node * 16 + c4];
    s.x += self.x; s.y += self.y; s.z += self.z; s.w += self.w;

    float4 o;
    if (PASS == 2) {
        float sc = g_dinv[node];
        int cb = c4 << 2;
        o.x = sc * s.x + __ldg(&b[cb + 0]);
        o.y = sc * s.y + __ldg(&b[cb + 1]);
        o.z = sc * s.z + __ldg(&b[cb + 2]);
        o.w = sc * s.w + __ldg(&b[cb + 3]);
    } else {
        float sc = g_dinv2[node];
        o.x = sc * s.x; o.y = sc * s.y; o.z = sc * s.z; o.w = sc * s.w;
    }
    uout[(size_t)node * 16 + c4] = o;
}

// ---------------------------------------------------------------------------
extern "C" void kernel_launch(void* const* d_in, const int* in_sizes, int n_in,
                              void* d_out, int out_size) {
    const float* x  = (const float*)d_in[0];   // [100000,128]
    const void*  ei = d_in[1];                 // [2, E] int32 or int64
    const float* W  = (const float*)d_in[2];   // [64,128]
    const float* b  = (const float*)d_in[3];   // [64]
    float* out = (float*)d_out;

    const int E = in_sizes[1] / 2;             // 1,600,000

    const int T = 256;
    const int nb = (N_NODES + T - 1) / T;
    const int eb = (E + T - 1) / T;

    k_detect<<<1, 256>>>((const int*)ei);

    // CSR build (counting sort by target)
    k_zero<<<nb, T>>>();
    k_hist<<<eb, T>>>(ei, E);
    k_scan1<<<SCAN_B, SCAN_T>>>();
    k_scan2<<<1, 128>>>();
    k_scan3<<<SCAN_B, SCAN_T>>>();
    k_scatter<<<eb, T>>>(ei, E);

    // Input transform (linear layer folded in front; needs g_dinv from scan)
    k_gemm<<<2048, T>>>(x, W);

    // 3 gather hops (16 nodes per 256-thread block)
    const int hb = (N_NODES + 15) / 16;
    k_hop<0><<<hb, T>>>(nullptr, b);
    k_hop<1><<<hb, T>>>(nullptr, b);
    k_hop<2><<<hb, T>>>(out, b);
}